// round 1
// baseline (speedup 1.0000x reference)
#include <cuda_runtime.h>

// CostVolume: out[b, o, y, x] = leaky( mean_c( c1[b,c,y,x] * warped[b,c,y+dy-4,x+dx-4] ) )
// o = dy*9+dx, dy,dx in [0,9). OOB warped = 0. leaky: r>=0 ? r : alpha*r.
// Shapes: B=8, C=192, H=128, W=160, 81 offsets.

#define SR 4
#define MAXOFF 9
#define NOFF 81
#define C_TOTAL 192
#define H_TOTAL 128
#define W_TOTAL 160
#define B_TOTAL 8

#define TW 32
#define TH 8
#define CC 8
#define HALO_W (TW + 2 * SR)   // 40
#define HALO_H (TH + 2 * SR)   // 16
#define NTHREADS 256

__global__ __launch_bounds__(NTHREADS, 2)
void costvol_kernel(const float* __restrict__ c1,
                    const float* __restrict__ warped,
                    const float* __restrict__ alpha,
                    float* __restrict__ out) {
    __shared__ float s_c1[CC][TH][TW];           // 8 KB
    __shared__ float s_w[CC][HALO_H][HALO_W];    // 20 KB

    const int tid = threadIdx.x;
    const int tx = tid & 31;          // 0..31 (x within tile)
    const int ty = tid >> 5;          // 0..7  (y within tile)
    const int x0 = blockIdx.x * TW;
    const int y0 = blockIdx.y * TH;
    const int b  = blockIdx.z;

    const float av = alpha[0];

    float acc[NOFF];
    #pragma unroll
    for (int i = 0; i < NOFF; i++) acc[i] = 0.0f;

    const size_t plane = (size_t)H_TOTAL * W_TOTAL;
    const size_t base_in = (size_t)b * C_TOTAL * plane;

    for (int cc = 0; cc < C_TOTAL; cc += CC) {
        // ---- stage c1 tile: CC*TH*TW = 2048 elems, 8 per thread ----
        #pragma unroll
        for (int i = 0; i < (CC * TH * TW) / NTHREADS; i++) {
            int idx = tid + i * NTHREADS;
            int c   = idx / (TH * TW);
            int rem = idx - c * (TH * TW);
            int yy  = rem / TW;
            int xx  = rem - yy * TW;
            s_c1[c][yy][xx] =
                c1[base_in + (size_t)(cc + c) * plane + (size_t)(y0 + yy) * W_TOTAL + (x0 + xx)];
        }
        // ---- stage warped halo: CC*16*40 = 5120 elems, 20 per thread ----
        #pragma unroll
        for (int i = 0; i < (CC * HALO_H * HALO_W) / NTHREADS; i++) {
            int idx = tid + i * NTHREADS;
            int c   = idx / (HALO_H * HALO_W);
            int rem = idx - c * (HALO_H * HALO_W);
            int yy  = rem / HALO_W;
            int xx  = rem - yy * HALO_W;
            int gy  = y0 + yy - SR;
            int gx  = x0 + xx - SR;
            float v = 0.0f;
            if (gy >= 0 && gy < H_TOTAL && gx >= 0 && gx < W_TOTAL)
                v = warped[base_in + (size_t)(cc + c) * plane + (size_t)gy * W_TOTAL + gx];
            s_w[c][yy][xx] = v;
        }
        __syncthreads();

        // ---- accumulate 81 correlations for this channel chunk ----
        #pragma unroll
        for (int c = 0; c < CC; c++) {
            const float a = s_c1[c][ty][tx];
            #pragma unroll
            for (int dy = 0; dy < MAXOFF; dy++) {
                const float* row = &s_w[c][ty + dy][tx];
                #pragma unroll
                for (int dx = 0; dx < MAXOFF; dx++) {
                    acc[dy * MAXOFF + dx] = fmaf(a, row[dx], acc[dy * MAXOFF + dx]);
                }
            }
        }
        __syncthreads();
    }

    // ---- epilogue: mean over C, leaky-relu, store ----
    const float inv = 1.0f / (float)C_TOTAL;
    const size_t obase = (size_t)b * NOFF * plane + (size_t)(y0 + ty) * W_TOTAL + (x0 + tx);
    #pragma unroll
    for (int o = 0; o < NOFF; o++) {
        float r = acc[o] * inv;
        out[obase + (size_t)o * plane] = (r >= 0.0f) ? r : av * r;
    }
}

extern "C" void kernel_launch(void* const* d_in, const int* in_sizes, int n_in,
                              void* d_out, int out_size) {
    const float* c1     = (const float*)d_in[0];
    const float* warped = (const float*)d_in[1];
    const float* alpha  = (const float*)d_in[2];
    float* out          = (float*)d_out;

    dim3 grid(W_TOTAL / TW, H_TOTAL / TH, B_TOTAL);  // (5, 16, 8) = 640 blocks
    dim3 block(NTHREADS);
    costvol_kernel<<<grid, block>>>(c1, warped, alpha, out);
}